// round 5
// baseline (speedup 1.0000x reference)
#include <cuda_runtime.h>
#include <cstddef>

// Problem constants (fixed shapes from setup_inputs)
#define C_    32
#define H_    192
#define W_    256
#define S_    9
#define G_    8
#define HW_   (H_*W_)            // 49152
#define HWS_  ((size_t)HW_*S_)   // 442368
#define CHWS_ ((size_t)C_*HWS_)

#define PX    16                 // pixels per CTA
#define TPB   (PX*8)             // 128 threads: (px, n) pairs

__device__ float g_M[C_*C_];     // Wp^T Wp (symmetric)
__device__ float g_v[C_];        // Wp^T bp

// ---------------- prep: M = Wp^T Wp, v = Wp^T bp ----------------
__global__ void prep_kernel(const float* __restrict__ Wp, const float* __restrict__ bp) {
    int tid = threadIdx.x;            // 1024 threads
    int i = tid >> 5, j = tid & 31;
    float m = 0.f;
    #pragma unroll
    for (int d = 0; d < C_; d++) m += Wp[d*C_ + i] * Wp[d*C_ + j];
    g_M[i*C_ + j] = m;
    if (tid < C_) {
        float vv = 0.f;
        #pragma unroll
        for (int d = 0; d < C_; d++) vv += Wp[d*C_ + tid] * bp[d];
        g_v[tid] = vv;
    }
}

// ---------------- main fused kernel ----------------
// Thread (px, j): px = tid>>3 pixel-in-CTA, j = tid&7 = source image index.
// Warp = 4 pixels x 8 j; all per-pixel sharing is intra-warp.
__global__ void __launch_bounds__(TPB, 6)
main_kernel(const float* __restrict__ f, float* __restrict__ out) {
    __shared__ float rm_sm[PX][33];    // ref mid values (padded: bank-conflict-free)
    __shared__ float wst[PX][289];     // att-scaled ref stash, 289 = 288+1 pad

    const int tid = threadIdx.x;
    const int px  = tid >> 3;
    const int j   = tid & 7;
    const int p   = blockIdx.x * PX + px;      // pixel index h*W + w
    const float* __restrict__ refp = f + (size_t)p * S_;

    // ---- pass 1a: gather r_mid (s=4) for this pixel's 32 channels (4 per thread) ----
    #pragma unroll
    for (int k = 0; k < 4; k++) {
        const int c = j*4 + k;
        rm_sm[px][c] = refp[(size_t)c * HWS_ + 4];
    }
    __syncwarp();

    // ---- pass 1b: tv = M*rm + v for own 4 channels; partial logits; stash raw ref ----
    float lp[S_];
    #pragma unroll
    for (int s = 0; s < S_; s++) lp[s] = 0.f;

    #pragma unroll
    for (int k = 0; k < 4; k++) {
        const int c = j*4 + k;
        float tvc = g_v[c];
        #pragma unroll
        for (int cj = 0; cj < C_; cj++) tvc += g_M[c*C_ + cj] * rm_sm[px][cj];
        float r[S_];
        #pragma unroll
        for (int s = 0; s < S_; s++) r[s] = refp[(size_t)c * HWS_ + s];
        #pragma unroll
        for (int s = 0; s < S_; s++) {
            lp[s] += tvc * r[s];
            wst[px][c*S_ + s] = r[s];
        }
    }

    // ---- reduce logits across the 8 threads of this pixel (contiguous 8-lane group) ----
    #pragma unroll
    for (int off = 4; off >= 1; off >>= 1) {
        #pragma unroll
        for (int s = 0; s < S_; s++)
            lp[s] += __shfl_xor_sync(0xffffffffu, lp[s], off);
    }

    // ---- softmax over s (shift-invariant terms dropped; computed redundantly per j) ----
    const float inv_sqrtC = 0.17677669529663687f;   // 1/sqrt(32)
    float mx = lp[0];
    #pragma unroll
    for (int s = 1; s < S_; s++) mx = fmaxf(mx, lp[s]);
    float att[S_], sum = 0.f;
    #pragma unroll
    for (int s = 0; s < S_; s++) { att[s] = __expf((lp[s] - mx) * inv_sqrtC); sum += att[s]; }
    const float isum = __frcp_rn(sum);
    #pragma unroll
    for (int s = 0; s < S_; s++) att[s] *= isum;

    // ---- rescale own 4 channels of the stash: w[c][s] = ref[c][s] * att[s] ----
    #pragma unroll
    for (int k = 0; k < 4; k++) {
        const int c = j*4 + k;
        #pragma unroll
        for (int s = 0; s < S_; s++) wst[px][c*S_ + s] *= att[s];
    }
    __syncwarp();

    // ---- pass 2: this thread streams src image n=j over all 32 channels ----
    const float* __restrict__ sb = f + (size_t)(j+1) * CHWS_ + (size_t)p * S_;
    #pragma unroll 1
    for (int g = 0; g < G_; g++) {
        float a = 0.f;
        #pragma unroll
        for (int cc = 0; cc < 4; cc++) {
            const int c = g*4 + cc;
            float w[S_], sp[S_];
            #pragma unroll
            for (int s = 0; s < S_; s++) sp[s] = __ldcs(sb + (size_t)c * HWS_ + s);
            #pragma unroll
            for (int s = 0; s < S_; s++) w[s] = wst[px][c*S_ + s];
            #pragma unroll
            for (int s = 0; s < S_; s++) a += w[s] * sp[s];
        }
        out[(size_t)(j*G_ + g) * HW_ + p] = a;
    }
}

extern "C" void kernel_launch(void* const* d_in, const int* in_sizes, int n_in,
                              void* d_out, int out_size) {
    // Identify inputs by element count: f = 127401984, Wp = 1024, bp = 32
    const float* f  = nullptr;
    const float* Wp = nullptr;
    const float* bp = nullptr;
    for (int i = 0; i < n_in; i++) {
        if      (in_sizes[i] == 127401984) f  = (const float*)d_in[i];
        else if (in_sizes[i] == 1024)      Wp = (const float*)d_in[i];
        else if (in_sizes[i] == 32)        bp = (const float*)d_in[i];
    }
    if (!f || !Wp || !bp) {  // fallback positional
        f  = (const float*)d_in[0];
        Wp = (const float*)d_in[1];
        bp = (const float*)d_in[2];
    }
    float* out = (float*)d_out;

    prep_kernel<<<1, 1024>>>(Wp, bp);
    main_kernel<<<HW_/PX, TPB>>>(f, out);
}

// round 8
// speedup vs baseline: 2.0480x; 2.0480x over previous
#include <cuda_runtime.h>
#include <cstddef>

// Problem constants (fixed shapes from setup_inputs)
#define C_    32
#define H_    192
#define W_    256
#define S_    9
#define G_    8
#define HW_   (H_*W_)            // 49152
#define HWS_  ((size_t)HW_*S_)   // 442368
#define CHWS_ ((size_t)C_*HWS_)

#define TPB 64

__device__ float g_M[C_*C_];     // Wp^T Wp (symmetric)
__device__ float g_v[C_];        // Wp^T bp

// ---------------- prep: M = Wp^T Wp, v = Wp^T bp ----------------
__global__ void prep_kernel(const float* __restrict__ Wp, const float* __restrict__ bp) {
    int tid = threadIdx.x;            // 1024 threads
    int i = tid >> 5, j = tid & 31;
    float m = 0.f;
    #pragma unroll
    for (int d = 0; d < C_; d++) m += Wp[d*C_ + i] * Wp[d*C_ + j];
    g_M[i*C_ + j] = m;
    if (tid < C_) {
        float vv = 0.f;
        #pragma unroll
        for (int d = 0; d < C_; d++) vv += Wp[d*C_ + tid] * bp[d];
        g_v[tid] = vv;
    }
}

// ---------------- main fused kernel: one thread per pixel, NO smem stash ----------------
// Warp = 32 consecutive pixels -> every warp-level load spans a tight 1152B
// window reused across the 9-s unroll (aggregate-coalesced, low L1 wavefronts).
__global__ void __launch_bounds__(TPB, 10)
main_kernel(const float* __restrict__ f, float* __restrict__ out) {
    const int p = blockIdx.x * TPB + threadIdx.x;   // pixel index h*W + w
    const float* __restrict__ refp = f + (size_t)p * S_;

    // ---- 1. r_mid (s=4) for all 32 channels ----
    float rm[C_];
    #pragma unroll
    for (int c = 0; c < C_; c++) rm[c] = __ldg(refp + (size_t)c * HWS_ + 4);

    // ---- 2. logits: l[s] = sum_c (M rm + v)[c] * r[c][s]  (tv folded, no array) ----
    float l[S_];
    #pragma unroll
    for (int s = 0; s < S_; s++) l[s] = 0.f;

    const float4* __restrict__ M4 = (const float4*)g_M;
    #pragma unroll 4
    for (int c = 0; c < C_; c++) {
        float tvc = g_v[c];
        #pragma unroll
        for (int q = 0; q < C_/4; q++) {
            float4 m4 = M4[c*(C_/4) + q];
            tvc += m4.x*rm[4*q] + m4.y*rm[4*q+1] + m4.z*rm[4*q+2] + m4.w*rm[4*q+3];
        }
        const float* rp = refp + (size_t)c * HWS_;
        #pragma unroll
        for (int s = 0; s < S_; s++) l[s] += tvc * __ldg(rp + s);
    }

    // ---- 3. softmax over s (shift-invariant terms dropped) ----
    const float inv_sqrtC = 0.17677669529663687f;   // 1/sqrt(32)
    float mx = l[0];
    #pragma unroll
    for (int s = 1; s < S_; s++) mx = fmaxf(mx, l[s]);
    float att[S_], sum = 0.f;
    #pragma unroll
    for (int s = 0; s < S_; s++) { att[s] = __expf((l[s] - mx) * inv_sqrtC); sum += att[s]; }
    const float isum = __frcp_rn(sum);
    #pragma unroll
    for (int s = 0; s < S_; s++) att[s] *= isum;

    // ---- 4. stream sources; ref row recomputed (L2-hot), src via evict-first ----
    #pragma unroll 1
    for (int g = 0; g < G_; g++) {
        float acc[8];
        #pragma unroll
        for (int n = 0; n < 8; n++) acc[n] = 0.f;
        #pragma unroll 1
        for (int cc = 0; cc < 4; cc++) {
            const int c = g*4 + cc;
            const float* rp = refp + (size_t)c * HWS_;
            float w[S_];
            #pragma unroll
            for (int s = 0; s < S_; s++) w[s] = __ldg(rp + s) * att[s];
            #pragma unroll
            for (int n = 0; n < 8; n++) {
                const float* __restrict__ sp =
                    f + (size_t)(n+1)*CHWS_ + (size_t)c*HWS_ + (size_t)p*S_;
                float a = 0.f;
                #pragma unroll
                for (int s = 0; s < S_; s++) a += w[s] * __ldcs(sp + s);
                acc[n] += a;
            }
        }
        #pragma unroll
        for (int n = 0; n < 8; n++)
            out[(size_t)(n*G_ + g)*HW_ + p] = acc[n];
    }
}

extern "C" void kernel_launch(void* const* d_in, const int* in_sizes, int n_in,
                              void* d_out, int out_size) {
    // Identify inputs by element count: f = 127401984, Wp = 1024, bp = 32
    const float* f  = nullptr;
    const float* Wp = nullptr;
    const float* bp = nullptr;
    for (int i = 0; i < n_in; i++) {
        if      (in_sizes[i] == 127401984) f  = (const float*)d_in[i];
        else if (in_sizes[i] == 1024)      Wp = (const float*)d_in[i];
        else if (in_sizes[i] == 32)        bp = (const float*)d_in[i];
    }
    if (!f || !Wp || !bp) {  // fallback positional
        f  = (const float*)d_in[0];
        Wp = (const float*)d_in[1];
        bp = (const float*)d_in[2];
    }
    float* out = (float*)d_out;

    prep_kernel<<<1, 1024>>>(Wp, bp);
    main_kernel<<<HW_/TPB, TPB>>>(f, out);
}